// round 15
// baseline (speedup 1.0000x reference)
#include <cuda_runtime.h>

// ---------------------------------------------------------------------------
// PPN on 3-level sparse voxel grid — FFMA2 convs + exact sparsity skips.
// R15: (1) float4 W staging in convs, (2) transposed neighbor tables
// ntr[k*N+n] (coalesced per-k index loads in convs + score/heads).
// output: points [N3,10] | ppn1 [N1,6] | ppn2 [N2,6] | mask1 [N1] | mask2 [N2]
// ---------------------------------------------------------------------------

#define N1_MAX 65536
#define N2_MAX 262144
#define N3_MAX 262144

__device__ float g_y1[(size_t)N1_MAX * 80];
__device__ float g_y2[(size_t)N2_MAX * 48];
__device__ float g_z[(size_t)N3_MAX * 16];
__device__ float g_pm2[N2_MAX];
__device__ float g_pm3[N3_MAX];
__device__ unsigned char g_act2[N2_MAX];
__device__ unsigned char g_act3[N3_MAX];
__device__ int g_ntr1[27 * (size_t)N1_MAX];
__device__ int g_ntr2[27 * (size_t)N2_MAX];
__device__ int g_ntr3[27 * (size_t)N3_MAX];

typedef unsigned long long ull;

__device__ __forceinline__ ull pk2(float x, float y) {
    ull r; asm("mov.b64 %0, {%1, %2};" : "=l"(r) : "f"(x), "f"(y)); return r;
}
__device__ __forceinline__ void fma2(ull& d, ull a, ull b) {
    asm("fma.rn.f32x2 %0, %1, %2, %0;" : "+l"(d) : "l"(a), "l"(b));
}
__device__ __forceinline__ float2 up2(ull v) {
    float a, b; asm("mov.b64 {%0, %1}, %2;" : "=f"(a), "=f"(b) : "l"(v));
    return make_float2(a, b);
}

// pm[i] = mask[parent[i]]
__global__ void premask(const int* __restrict__ parent,
                        const float* __restrict__ mask,
                        float* __restrict__ pm, int N) {
    int i = blockIdx.x * blockDim.x + threadIdx.x;
    if (i < N) pm[i] = mask[parent[i]];
}

// ntr[k*N+n] = nbr[n*27+k]  (coalesced write, strided read)
__global__ void transpose_nbr(const int* __restrict__ nbr,
                              int* __restrict__ ntr, int N) {
    int i = blockIdx.x * blockDim.x + threadIdx.x;
    if (i < 27 * N) {
        int k = i / N, n = i - k * N;
        ntr[i] = nbr[n * 27 + k];
    }
}

// ---------------------------------------------------------------------------
// Unmasked conv (level 1) — cooperative staging per (k, CIN-chunk).
// ---------------------------------------------------------------------------
template <int CIN, int COUT, int TN, int RN, int RD, int NTX, int CCH, int MINB>
__global__ __launch_bounds__(NTX*(TN/RN), MINB)
void subconv2(const float* __restrict__ feat, const int* __restrict__ ntr,
              const float* __restrict__ W, float* __restrict__ out, int N) {
    constexpr int CP = CCH + 4;
    constexpr int NTY = TN / RN;
    constexpr int NTH = NTX * NTY;
    static_assert(NTH == 128, "128 threads");
    static_assert(CIN % CCH == 0 && CCH % 4 == 0 && RD % 4 == 0, "");
    constexpr int NH = CIN / CCH;
    constexpr int VEC = CCH / 4;
    constexpr int W4 = CCH * COUT / 4;
    constexpr int NP = RD / 2;
    constexpr int NU = RD / 4;

    extern __shared__ float sh[];
    float* sW = sh;
    float* sF = sh + CCH * COUT;
    __shared__ int sIdx[TN];

    const int tid = threadIdx.x;
    const int tx = tid % NTX, ty = tid / NTX;
    const int n0 = blockIdx.x * TN;
    const int nb = ty * RN, db = tx * RD;

    ull acc[RN][NP];
#pragma unroll
    for (int i = 0; i < RN; ++i)
#pragma unroll
        for (int p = 0; p < NP; ++p) acc[i][p] = 0ULL;

    for (int k = 0; k < 27; ++k) {
        const int* nk = ntr + (size_t)k * N;
        for (int i = tid; i < TN; i += NTH) {
            int n = n0 + i;
            sIdx[i] = (n < N) ? nk[n] : N;
        }
        const float* Wk = W + (size_t)k * CIN * COUT;
#pragma unroll
        for (int h = 0; h < NH; ++h) {
            __syncthreads();
            {
                const float4* Wk4 = reinterpret_cast<const float4*>(
                    Wk + h * CCH * COUT);
                float4* sW4 = reinterpret_cast<float4*>(sW);
                for (int i = tid; i < W4; i += NTH) sW4[i] = Wk4[i];
            }
            const int bc = h * CCH;
            for (int i = tid; i < TN * VEC; i += NTH) {
                int n = i / VEC, c4 = (i - n * VEC) * 4;
                int idx = sIdx[n];
                float4 v = make_float4(0.f, 0.f, 0.f, 0.f);
                if ((unsigned)idx < (unsigned)N)
                    v = *reinterpret_cast<const float4*>(
                        feat + (size_t)idx * CIN + bc + c4);
                *reinterpret_cast<float4*>(sF + n * CP + c4) = v;
            }
            __syncthreads();

#pragma unroll
            for (int c4 = 0; c4 < CCH; c4 += 4) {
                float4 A[RN];
#pragma unroll
                for (int i = 0; i < RN; ++i)
                    A[i] = *reinterpret_cast<const float4*>(
                        sF + (nb + i) * CP + c4);
#pragma unroll
                for (int cc = 0; cc < 4; ++cc) {
                    ull as[RN];
#pragma unroll
                    for (int i = 0; i < RN; ++i) {
                        float v = (cc == 0) ? A[i].x : (cc == 1) ? A[i].y
                                 : (cc == 2) ? A[i].z : A[i].w;
                        as[i] = pk2(v, v);
                    }
                    const float* wrow = sW + (c4 + cc) * COUT + db;
#pragma unroll
                    for (int u = 0; u < NU; ++u) {
                        float4 B = *reinterpret_cast<const float4*>(wrow + 4 * u);
                        ull b0 = pk2(B.x, B.y), b1 = pk2(B.z, B.w);
#pragma unroll
                        for (int i = 0; i < RN; ++i) {
                            fma2(acc[i][2 * u], as[i], b0);
                            fma2(acc[i][2 * u + 1], as[i], b1);
                        }
                    }
                }
            }
        }
    }

#pragma unroll
    for (int i = 0; i < RN; ++i) {
        int n = n0 + nb + i;
        if (n < N) {
#pragma unroll
            for (int u = 0; u < NU; ++u) {
                float2 p0 = up2(acc[i][2 * u]), p1 = up2(acc[i][2 * u + 1]);
                float4 o = make_float4(p0.x, p0.y, p1.x, p1.y);
                *reinterpret_cast<float4*>(out + (size_t)n * COUT + db + 4 * u) = o;
            }
        }
    }
}

// ---------------------------------------------------------------------------
// Masked conv (levels 2/3): out[n,d] = sum_k sum_c pm[j]*feat[j,c]*W[k,c,d],
// j = ntr[k*N+n]. All-zero-mask k-stages SKIPPED exactly; emits act[n].
// ---------------------------------------------------------------------------
template <int CIN, int COUT, int TN, int RN, int RD, int NTX, int MINB>
__global__ __launch_bounds__(NTX*(TN/RN), MINB)
void subconv2m(const float* __restrict__ feat, const int* __restrict__ ntr,
               const float* __restrict__ W, const float* __restrict__ pm,
               float* __restrict__ out, unsigned char* __restrict__ act,
               int N) {
    constexpr int CP = CIN + 4;
    constexpr int NTY = TN / RN;
    constexpr int NTH = NTX * NTY;
    static_assert(NTH == 128 || NTH == 256, "thread count");
    static_assert(CIN % 4 == 0 && RD % 4 == 0 && TN % NTH == 0, "");
    constexpr int VEC = CIN / 4;
    constexpr int W4 = CIN * COUT / 4;
    constexpr int NP = RD / 2;
    constexpr int NU = RD / 4;
    constexpr int RPT = TN / NTH;

    extern __shared__ float sh[];
    float* sW = sh;                        // [CIN][COUT]
    float* sF = sh + CIN * COUT;           // [TN][CP]
    __shared__ int sIdx[TN];
    __shared__ float sM[TN];

    const int tid = threadIdx.x;
    const int tx = tid % NTX, ty = tid / NTX;
    const int n0 = blockIdx.x * TN;
    const int nb = ty * RN, db = tx * RD;

    ull acc[RN][NP];
#pragma unroll
    for (int i = 0; i < RN; ++i)
#pragma unroll
        for (int p = 0; p < NP; ++p) acc[i][p] = 0ULL;

    int rowAct[RPT];
#pragma unroll
    for (int j = 0; j < RPT; ++j) rowAct[j] = 0;

    for (int k = 0; k < 27; ++k) {
        const int* nk = ntr + (size_t)k * N;
        int myAny = 0;
#pragma unroll
        for (int j = 0; j < RPT; ++j) {
            int i = tid + j * NTH;
            int n = n0 + i;
            int idx = (n < N) ? nk[n] : N;
            float m = ((unsigned)idx < (unsigned)N) ? pm[idx] : 0.f;
            sIdx[i] = idx;
            sM[i] = m;
            int nz = (m != 0.f);
            myAny |= nz;
            rowAct[j] |= nz;
        }
        if (!__syncthreads_or(myAny)) continue;   // exact: zero contribution

        {
            const float4* Wk4 = reinterpret_cast<const float4*>(
                W + (size_t)k * CIN * COUT);
            float4* sW4 = reinterpret_cast<float4*>(sW);
            for (int i = tid; i < W4; i += NTH) sW4[i] = Wk4[i];
        }
        for (int i = tid; i < TN * VEC; i += NTH) {
            int n = i / VEC, c4 = (i - n * VEC) * 4;
            int idx = sIdx[n];
            float4 v = make_float4(0.f, 0.f, 0.f, 0.f);
            if ((unsigned)idx < (unsigned)N) {
                float m = sM[n];
                if (m != 0.f) {
                    v = *reinterpret_cast<const float4*>(
                        feat + (size_t)idx * CIN + c4);
                    v.x *= m; v.y *= m; v.z *= m; v.w *= m;
                }
            }
            *reinterpret_cast<float4*>(sF + n * CP + c4) = v;
        }
        __syncthreads();

#pragma unroll
        for (int c4 = 0; c4 < CIN; c4 += 4) {
            float4 A[RN];
#pragma unroll
            for (int i = 0; i < RN; ++i)
                A[i] = *reinterpret_cast<const float4*>(sF + (nb + i) * CP + c4);
#pragma unroll
            for (int cc = 0; cc < 4; ++cc) {
                ull as[RN];
#pragma unroll
                for (int i = 0; i < RN; ++i) {
                    float v = (cc == 0) ? A[i].x : (cc == 1) ? A[i].y
                             : (cc == 2) ? A[i].z : A[i].w;
                    as[i] = pk2(v, v);
                }
                const float* wrow = sW + (c4 + cc) * COUT + db;
#pragma unroll
                for (int u = 0; u < NU; ++u) {
                    float4 B = *reinterpret_cast<const float4*>(wrow + 4 * u);
                    ull b0 = pk2(B.x, B.y), b1 = pk2(B.z, B.w);
#pragma unroll
                    for (int i = 0; i < RN; ++i) {
                        fma2(acc[i][2 * u], as[i], b0);
                        fma2(acc[i][2 * u + 1], as[i], b1);
                    }
                }
            }
        }
    }

#pragma unroll
    for (int j = 0; j < RPT; ++j) {
        int n = n0 + tid + j * NTH;
        if (n < N) act[n] = (unsigned char)rowAct[j];
    }

#pragma unroll
    for (int i = 0; i < RN; ++i) {
        int n = n0 + nb + i;
        if (n < N) {
#pragma unroll
            for (int u = 0; u < NU; ++u) {
                float2 p0 = up2(acc[i][2 * u]), p1 = up2(acc[i][2 * u + 1]);
                float4 o = make_float4(p0.x, p0.y, p1.x, p1.y);
                *reinterpret_cast<float4*>(out + (size_t)n * COUT + db + 4 * u) = o;
            }
        }
    }
}

// ---------------------------------------------------------------------------
// Score head (Cout=2) + ppn concat + threshold mask — batched pointer-chase
// with transposed indices (coalesced per-k loads).
// softmax([s0,s1])[1] > 0.8  <=>  1/(1+exp(s0-s1)) > 0.8
// ---------------------------------------------------------------------------
template <int CIN, bool ACT>
__global__ void score_ppn_mask(const float* __restrict__ feat,
                               const int* __restrict__ ntr,
                               const float* __restrict__ Ws,
                               const int* __restrict__ coords,
                               const unsigned char* __restrict__ act,
                               float* __restrict__ ppn,
                               float* __restrict__ mask, int N) {
    __shared__ float sW[27 * 2 * CIN];  // [k][d][c]
    for (int i = threadIdx.x; i < 27 * CIN * 2; i += blockDim.x) {
        int k = i / (CIN * 2);
        int r = i - k * (CIN * 2);
        int c = r >> 1, d = r & 1;
        sW[(k * 2 + d) * CIN + c] = Ws[i];
    }
    __syncthreads();
    int n = blockIdx.x * blockDim.x + threadIdx.x;
    if (n >= N) return;

    int idxs[27];
#pragma unroll
    for (int k = 0; k < 27; ++k) idxs[k] = ntr[(size_t)k * N + n];
    bool live[27];
#pragma unroll
    for (int k = 0; k < 27; ++k) {
        bool v = (unsigned)idxs[k] < (unsigned)N;
        if (ACT) v = v && (act[idxs[k]] != 0);
        live[k] = v;
    }

    float a0 = 0.f, a1 = 0.f;
#pragma unroll
    for (int k = 0; k < 27; ++k) {
        if (live[k]) {
            const float4* fr = reinterpret_cast<const float4*>(feat + (size_t)idxs[k] * CIN);
            const float4* w0 = reinterpret_cast<const float4*>(sW + (k * 2 + 0) * CIN);
            const float4* w1 = reinterpret_cast<const float4*>(sW + (k * 2 + 1) * CIN);
#pragma unroll
            for (int j = 0; j < CIN / 4; ++j) {
                float4 v = fr[j], x = w0[j], y = w1[j];
                a0 += v.x * x.x + v.y * x.y + v.z * x.z + v.w * x.w;
                a1 += v.x * y.x + v.y * y.y + v.z * y.z + v.w * y.w;
            }
        }
    }
    ppn[(size_t)n * 6 + 0] = (float)coords[n * 4 + 0];
    ppn[(size_t)n * 6 + 1] = (float)coords[n * 4 + 1];
    ppn[(size_t)n * 6 + 2] = (float)coords[n * 4 + 2];
    ppn[(size_t)n * 6 + 3] = (float)coords[n * 4 + 3];
    ppn[(size_t)n * 6 + 4] = a0;
    ppn[(size_t)n * 6 + 5] = a1;
    float p = 1.f / (1.f + expf(a0 - a1));
    mask[n] = (p > 0.8f) ? 1.f : 0.f;
}

// Fine heads fused, batched + transposed indices: points[n, 0:3|3:5|5:10].
__global__ void heads_kernel(const float* __restrict__ z,
                             const int* __restrict__ ntr,
                             const float* __restrict__ Wp,
                             const float* __restrict__ Wsc,
                             const float* __restrict__ Wt,
                             const unsigned char* __restrict__ act,
                             float* __restrict__ points, int N) {
    __shared__ float sW[27 * 10 * 16];  // [k][d][c]
    for (int i = threadIdx.x; i < 27 * 16 * 3; i += blockDim.x) {
        int k = i / 48; int r = i - k * 48; int c = r / 3; int d = r - c * 3;
        sW[(k * 10 + d) * 16 + c] = Wp[i];
    }
    for (int i = threadIdx.x; i < 27 * 16 * 2; i += blockDim.x) {
        int k = i / 32; int r = i - k * 32; int c = r >> 1; int d = r & 1;
        sW[(k * 10 + 3 + d) * 16 + c] = Wsc[i];
    }
    for (int i = threadIdx.x; i < 27 * 16 * 5; i += blockDim.x) {
        int k = i / 80; int r = i - k * 80; int c = r / 5; int d = r - c * 5;
        sW[(k * 10 + 5 + d) * 16 + c] = Wt[i];
    }
    __syncthreads();
    int n = blockIdx.x * blockDim.x + threadIdx.x;
    if (n >= N) return;

    int idxs[27];
#pragma unroll
    for (int k = 0; k < 27; ++k) idxs[k] = ntr[(size_t)k * N + n];
    bool live[27];
#pragma unroll
    for (int k = 0; k < 27; ++k)
        live[k] = ((unsigned)idxs[k] < (unsigned)N) && (act[idxs[k]] != 0);

    float acc[10];
#pragma unroll
    for (int d = 0; d < 10; ++d) acc[d] = 0.f;

#pragma unroll
    for (int k = 0; k < 27; ++k) {
        if (live[k]) {
            const float4* zr = reinterpret_cast<const float4*>(z + (size_t)idxs[k] * 16);
            float4 v0 = zr[0], v1 = zr[1], v2 = zr[2], v3 = zr[3];
#pragma unroll
            for (int d = 0; d < 10; ++d) {
                const float4* wr = reinterpret_cast<const float4*>(sW + (k * 10 + d) * 16);
                float4 w0 = wr[0], w1 = wr[1], w2 = wr[2], w3 = wr[3];
                acc[d] += v0.x * w0.x + v0.y * w0.y + v0.z * w0.z + v0.w * w0.w
                        + v1.x * w1.x + v1.y * w1.y + v1.z * w1.z + v1.w * w1.w
                        + v2.x * w2.x + v2.y * w2.y + v2.z * w2.z + v2.w * w2.w
                        + v3.x * w3.x + v3.y * w3.y + v3.z * w3.z + v3.w * w3.w;
            }
        }
    }
#pragma unroll
    for (int d = 0; d < 10; ++d) points[(size_t)n * 10 + d] = acc[d];
}

// ---------------------------------------------------------------------------
static constexpr int smem_sub(int CCH, int COUT, int TN) {
    return (CCH * COUT + TN * (CCH + 4) + 32) * (int)sizeof(float);
}

extern "C" void kernel_launch(void* const* d_in, const int* in_sizes, int n_in,
                              void* d_out, int out_size) {
    const float* feat1 = (const float*)d_in[0];
    const float* feat2 = (const float*)d_in[1];
    const float* feat3 = (const float*)d_in[2];
    const float* W1  = (const float*)d_in[3];
    const float* W1s = (const float*)d_in[4];
    const float* W2  = (const float*)d_in[5];
    const float* W2s = (const float*)d_in[6];
    const float* W3  = (const float*)d_in[7];
    const float* W3p = (const float*)d_in[8];
    const float* W3s = (const float*)d_in[9];
    const float* W3t = (const float*)d_in[10];
    const int* nbr1 = (const int*)d_in[11];
    const int* nbr2 = (const int*)d_in[12];
    const int* nbr3 = (const int*)d_in[13];
    const int* parent2 = (const int*)d_in[14];
    const int* parent3 = (const int*)d_in[15];
    const int* coords1 = (const int*)d_in[16];
    const int* coords2 = (const int*)d_in[17];

    const int N1 = in_sizes[0] / 80;
    const int N2 = in_sizes[1] / 48;
    const int N3 = in_sizes[2] / 16;

    float* out = (float*)d_out;
    float* points = out;
    float* ppn1  = points + (size_t)N3 * 10;
    float* ppn2  = ppn1 + (size_t)N1 * 6;
    float* mask1 = ppn2 + (size_t)N2 * 6;
    float* mask2 = mask1 + N1;

    float *y1, *y2, *z, *pm2, *pm3;
    unsigned char *act2, *act3;
    int *ntr1, *ntr2, *ntr3;
    cudaGetSymbolAddress((void**)&y1, g_y1);
    cudaGetSymbolAddress((void**)&y2, g_y2);
    cudaGetSymbolAddress((void**)&z, g_z);
    cudaGetSymbolAddress((void**)&pm2, g_pm2);
    cudaGetSymbolAddress((void**)&pm3, g_pm3);
    cudaGetSymbolAddress((void**)&act2, g_act2);
    cudaGetSymbolAddress((void**)&act3, g_act3);
    cudaGetSymbolAddress((void**)&ntr1, g_ntr1);
    cudaGetSymbolAddress((void**)&ntr2, g_ntr2);
    cudaGetSymbolAddress((void**)&ntr3, g_ntr3);

    // Neighbor-table transposes (independent of everything else; run first)
    transpose_nbr<<<(27 * N1 + 255) / 256, 256>>>(nbr1, ntr1, N1);
    transpose_nbr<<<(27 * N2 + 255) / 256, 256>>>(nbr2, ntr2, N2);
    transpose_nbr<<<(27 * N3 + 255) / 256, 256>>>(nbr3, ntr3, N3);

    // --- Level 1 (coarse, 80ch): chunked CCH=40, 35.4KB smem, 4 blk/SM ---
    subconv2<80, 80, 128, 4, 20, 4, 40, 4>
        <<<(N1 + 127) / 128, 128, smem_sub(40, 80, 128)>>>(feat1, ntr1, W1, y1, N1);
    score_ppn_mask<80, false><<<(N1 + 255) / 256, 256>>>(
        y1, ntr1, W1s, coords1, nullptr, ppn1, mask1, N1);

    // --- Level 2 (mid, 48ch): pm2 precompute + proven conv (minBlocks=5) ---
    premask<<<(N2 + 255) / 256, 256>>>(parent2, mask1, pm2, N2);
    subconv2m<48, 48, 128, 4, 12, 4, 5>
        <<<(N2 + 127) / 128, 128, smem_sub(48, 48, 128)>>>(
            feat2, ntr2, W2, pm2, y2, act2, N2);
    score_ppn_mask<48, true><<<(N2 + 255) / 256, 256>>>(
        y2, ntr2, W2s, coords2, act2, ppn2, mask2, N2);

    // --- Level 3 (fine, 16ch): pm3 precompute + masked conv + act flags ---
    premask<<<(N3 + 255) / 256, 256>>>(parent3, mask2, pm3, N3);
    subconv2m<16, 16, 256, 8, 4, 4, 1>
        <<<(N3 + 255) / 256, 128, smem_sub(16, 16, 256)>>>(
            feat3, ntr3, W3, pm3, z, act3, N3);
    heads_kernel<<<(N3 + 255) / 256, 256>>>(
        z, ntr3, W3p, W3s, W3t, act3, points, N3);
}

// round 16
// speedup vs baseline: 1.3204x; 1.3204x over previous
#include <cuda_runtime.h>

// ---------------------------------------------------------------------------
// PPN on 3-level sparse voxel grid — FFMA2 convs + exact sparsity skips.
// R16: transposed tables REVERTED (their build cost > benefit). L1 conv is
// K-SPLIT 4 ways across blockIdx.y (N1~16k gave <1 wave at TN=128) with a
// float4 add-reduce of the 4 partials. pm-precompute + float4 W staging kept.
// output: points [N3,10] | ppn1 [N1,6] | ppn2 [N2,6] | mask1 [N1] | mask2 [N2]
// ---------------------------------------------------------------------------

#define N1_MAX 65536
#define N2_MAX 262144
#define N3_MAX 262144
#define KSPLIT 4

__device__ float g_y1[(size_t)N1_MAX * 80];
__device__ float g_y1p[(size_t)KSPLIT * N1_MAX * 80];
__device__ float g_y2[(size_t)N2_MAX * 48];
__device__ float g_z[(size_t)N3_MAX * 16];
__device__ float g_pm2[N2_MAX];
__device__ float g_pm3[N3_MAX];
__device__ unsigned char g_act2[N2_MAX];
__device__ unsigned char g_act3[N3_MAX];

typedef unsigned long long ull;

__device__ __forceinline__ ull pk2(float x, float y) {
    ull r; asm("mov.b64 %0, {%1, %2};" : "=l"(r) : "f"(x), "f"(y)); return r;
}
__device__ __forceinline__ void fma2(ull& d, ull a, ull b) {
    asm("fma.rn.f32x2 %0, %1, %2, %0;" : "+l"(d) : "l"(a), "l"(b));
}
__device__ __forceinline__ float2 up2(ull v) {
    float a, b; asm("mov.b64 {%0, %1}, %2;" : "=f"(a), "=f"(b) : "l"(v));
    return make_float2(a, b);
}

// pm[i] = mask[parent[i]]
__global__ void premask(const int* __restrict__ parent,
                        const float* __restrict__ mask,
                        float* __restrict__ pm, int N) {
    int i = blockIdx.x * blockDim.x + threadIdx.x;
    if (i < N) pm[i] = mask[parent[i]];
}

// y[i] = sum of KSPLIT partials (float4-vectorized; total = N*COUT/4 chunks)
__global__ void add_partials(const float* __restrict__ p, size_t pstride,
                             float* __restrict__ y, int total4) {
    int i = blockIdx.x * blockDim.x + threadIdx.x;
    if (i >= total4) return;
    float4 s = reinterpret_cast<const float4*>(p)[i];
#pragma unroll
    for (int j = 1; j < KSPLIT; ++j) {
        float4 v = reinterpret_cast<const float4*>(p + j * pstride)[i];
        s.x += v.x; s.y += v.y; s.z += v.z; s.w += v.w;
    }
    reinterpret_cast<float4*>(y)[i] = s;
}

// ---------------------------------------------------------------------------
// Unmasked conv, K-SPLIT (level 1): blockIdx.y = ks handles k in
// [7ks, min(27, 7ks+7)), accumulating into its own partial buffer.
// ---------------------------------------------------------------------------
template <int CIN, int COUT, int TN, int RN, int RD, int NTX, int CCH, int MINB>
__global__ __launch_bounds__(NTX*(TN/RN), MINB)
void subconv2k(const float* __restrict__ feat, const int* __restrict__ nbr,
               const float* __restrict__ W, float* __restrict__ outp,
               size_t pstride, int N) {
    constexpr int CP = CCH + 4;
    constexpr int NTY = TN / RN;
    constexpr int NTH = NTX * NTY;
    static_assert(NTH == 128, "128 threads");
    static_assert(CIN % CCH == 0 && CCH % 4 == 0 && RD % 4 == 0, "");
    constexpr int NH = CIN / CCH;
    constexpr int VEC = CCH / 4;
    constexpr int W4 = CCH * COUT / 4;
    constexpr int NP = RD / 2;
    constexpr int NU = RD / 4;

    extern __shared__ float sh[];
    float* sW = sh;
    float* sF = sh + CCH * COUT;
    __shared__ int sIdx[TN];

    const int tid = threadIdx.x;
    const int tx = tid % NTX, ty = tid / NTX;
    const int n0 = blockIdx.x * TN;
    const int nb = ty * RN, db = tx * RD;
    const int ks = blockIdx.y;
    const int kBeg = ks * 7, kEnd = (kBeg + 7 < 27) ? kBeg + 7 : 27;
    float* out = outp + (size_t)ks * pstride;

    ull acc[RN][NP];
#pragma unroll
    for (int i = 0; i < RN; ++i)
#pragma unroll
        for (int p = 0; p < NP; ++p) acc[i][p] = 0ULL;

    for (int k = kBeg; k < kEnd; ++k) {
        for (int i = tid; i < TN; i += NTH) {
            int n = n0 + i;
            sIdx[i] = (n < N) ? nbr[n * 27 + k] : N;
        }
        const float* Wk = W + (size_t)k * CIN * COUT;
#pragma unroll
        for (int h = 0; h < NH; ++h) {
            __syncthreads();
            {
                const float4* Wk4 = reinterpret_cast<const float4*>(
                    Wk + h * CCH * COUT);
                float4* sW4 = reinterpret_cast<float4*>(sW);
                for (int i = tid; i < W4; i += NTH) sW4[i] = Wk4[i];
            }
            const int bc = h * CCH;
            for (int i = tid; i < TN * VEC; i += NTH) {
                int n = i / VEC, c4 = (i - n * VEC) * 4;
                int idx = sIdx[n];
                float4 v = make_float4(0.f, 0.f, 0.f, 0.f);
                if ((unsigned)idx < (unsigned)N)
                    v = *reinterpret_cast<const float4*>(
                        feat + (size_t)idx * CIN + bc + c4);
                *reinterpret_cast<float4*>(sF + n * CP + c4) = v;
            }
            __syncthreads();

#pragma unroll
            for (int c4 = 0; c4 < CCH; c4 += 4) {
                float4 A[RN];
#pragma unroll
                for (int i = 0; i < RN; ++i)
                    A[i] = *reinterpret_cast<const float4*>(
                        sF + (nb + i) * CP + c4);
#pragma unroll
                for (int cc = 0; cc < 4; ++cc) {
                    ull as[RN];
#pragma unroll
                    for (int i = 0; i < RN; ++i) {
                        float v = (cc == 0) ? A[i].x : (cc == 1) ? A[i].y
                                 : (cc == 2) ? A[i].z : A[i].w;
                        as[i] = pk2(v, v);
                    }
                    const float* wrow = sW + (c4 + cc) * COUT + db;
#pragma unroll
                    for (int u = 0; u < NU; ++u) {
                        float4 B = *reinterpret_cast<const float4*>(wrow + 4 * u);
                        ull b0 = pk2(B.x, B.y), b1 = pk2(B.z, B.w);
#pragma unroll
                        for (int i = 0; i < RN; ++i) {
                            fma2(acc[i][2 * u], as[i], b0);
                            fma2(acc[i][2 * u + 1], as[i], b1);
                        }
                    }
                }
            }
        }
    }

#pragma unroll
    for (int i = 0; i < RN; ++i) {
        int n = n0 + nb + i;
        if (n < N) {
#pragma unroll
            for (int u = 0; u < NU; ++u) {
                float2 p0 = up2(acc[i][2 * u]), p1 = up2(acc[i][2 * u + 1]);
                float4 o = make_float4(p0.x, p0.y, p1.x, p1.y);
                *reinterpret_cast<float4*>(out + (size_t)n * COUT + db + 4 * u) = o;
            }
        }
    }
}

// ---------------------------------------------------------------------------
// Masked conv (levels 2/3): out[n,d] = sum_k sum_c pm[j]*feat[j,c]*W[k,c,d],
// j=nbr[n,k]. All-zero-mask k-stages SKIPPED exactly; emits act[n].
// ---------------------------------------------------------------------------
template <int CIN, int COUT, int TN, int RN, int RD, int NTX, int MINB>
__global__ __launch_bounds__(NTX*(TN/RN), MINB)
void subconv2m(const float* __restrict__ feat, const int* __restrict__ nbr,
               const float* __restrict__ W, const float* __restrict__ pm,
               float* __restrict__ out, unsigned char* __restrict__ act,
               int N) {
    constexpr int CP = CIN + 4;
    constexpr int NTY = TN / RN;
    constexpr int NTH = NTX * NTY;
    static_assert(NTH == 128 || NTH == 256, "thread count");
    static_assert(CIN % 4 == 0 && RD % 4 == 0 && TN % NTH == 0, "");
    constexpr int VEC = CIN / 4;
    constexpr int W4 = CIN * COUT / 4;
    constexpr int NP = RD / 2;
    constexpr int NU = RD / 4;
    constexpr int RPT = TN / NTH;

    extern __shared__ float sh[];
    float* sW = sh;                        // [CIN][COUT]
    float* sF = sh + CIN * COUT;           // [TN][CP]
    __shared__ int sIdx[TN];
    __shared__ float sM[TN];

    const int tid = threadIdx.x;
    const int tx = tid % NTX, ty = tid / NTX;
    const int n0 = blockIdx.x * TN;
    const int nb = ty * RN, db = tx * RD;

    ull acc[RN][NP];
#pragma unroll
    for (int i = 0; i < RN; ++i)
#pragma unroll
        for (int p = 0; p < NP; ++p) acc[i][p] = 0ULL;

    int rowAct[RPT];
#pragma unroll
    for (int j = 0; j < RPT; ++j) rowAct[j] = 0;

    for (int k = 0; k < 27; ++k) {
        int myAny = 0;
#pragma unroll
        for (int j = 0; j < RPT; ++j) {
            int i = tid + j * NTH;
            int n = n0 + i;
            int idx = (n < N) ? nbr[n * 27 + k] : N;
            float m = ((unsigned)idx < (unsigned)N) ? pm[idx] : 0.f;
            sIdx[i] = idx;
            sM[i] = m;
            int nz = (m != 0.f);
            myAny |= nz;
            rowAct[j] |= nz;
        }
        if (!__syncthreads_or(myAny)) continue;   // exact: zero contribution

        {
            const float4* Wk4 = reinterpret_cast<const float4*>(
                W + (size_t)k * CIN * COUT);
            float4* sW4 = reinterpret_cast<float4*>(sW);
            for (int i = tid; i < W4; i += NTH) sW4[i] = Wk4[i];
        }
        for (int i = tid; i < TN * VEC; i += NTH) {
            int n = i / VEC, c4 = (i - n * VEC) * 4;
            int idx = sIdx[n];
            float4 v = make_float4(0.f, 0.f, 0.f, 0.f);
            if ((unsigned)idx < (unsigned)N) {
                float m = sM[n];
                if (m != 0.f) {
                    v = *reinterpret_cast<const float4*>(
                        feat + (size_t)idx * CIN + c4);
                    v.x *= m; v.y *= m; v.z *= m; v.w *= m;
                }
            }
            *reinterpret_cast<float4*>(sF + n * CP + c4) = v;
        }
        __syncthreads();

#pragma unroll
        for (int c4 = 0; c4 < CIN; c4 += 4) {
            float4 A[RN];
#pragma unroll
            for (int i = 0; i < RN; ++i)
                A[i] = *reinterpret_cast<const float4*>(sF + (nb + i) * CP + c4);
#pragma unroll
            for (int cc = 0; cc < 4; ++cc) {
                ull as[RN];
#pragma unroll
                for (int i = 0; i < RN; ++i) {
                    float v = (cc == 0) ? A[i].x : (cc == 1) ? A[i].y
                             : (cc == 2) ? A[i].z : A[i].w;
                    as[i] = pk2(v, v);
                }
                const float* wrow = sW + (c4 + cc) * COUT + db;
#pragma unroll
                for (int u = 0; u < NU; ++u) {
                    float4 B = *reinterpret_cast<const float4*>(wrow + 4 * u);
                    ull b0 = pk2(B.x, B.y), b1 = pk2(B.z, B.w);
#pragma unroll
                    for (int i = 0; i < RN; ++i) {
                        fma2(acc[i][2 * u], as[i], b0);
                        fma2(acc[i][2 * u + 1], as[i], b1);
                    }
                }
            }
        }
    }

#pragma unroll
    for (int j = 0; j < RPT; ++j) {
        int n = n0 + tid + j * NTH;
        if (n < N) act[n] = (unsigned char)rowAct[j];
    }

#pragma unroll
    for (int i = 0; i < RN; ++i) {
        int n = n0 + nb + i;
        if (n < N) {
#pragma unroll
            for (int u = 0; u < NU; ++u) {
                float2 p0 = up2(acc[i][2 * u]), p1 = up2(acc[i][2 * u + 1]);
                float4 o = make_float4(p0.x, p0.y, p1.x, p1.y);
                *reinterpret_cast<float4*>(out + (size_t)n * COUT + db + 4 * u) = o;
            }
        }
    }
}

// ---------------------------------------------------------------------------
// Score head (Cout=2) + ppn concat + threshold mask — batched pointer-chase.
// softmax([s0,s1])[1] > 0.8  <=>  1/(1+exp(s0-s1)) > 0.8
// ---------------------------------------------------------------------------
template <int CIN, bool ACT>
__global__ void score_ppn_mask(const float* __restrict__ feat,
                               const int* __restrict__ nbr,
                               const float* __restrict__ Ws,
                               const int* __restrict__ coords,
                               const unsigned char* __restrict__ act,
                               float* __restrict__ ppn,
                               float* __restrict__ mask, int N) {
    __shared__ float sW[27 * 2 * CIN];  // [k][d][c]
    for (int i = threadIdx.x; i < 27 * CIN * 2; i += blockDim.x) {
        int k = i / (CIN * 2);
        int r = i - k * (CIN * 2);
        int c = r >> 1, d = r & 1;
        sW[(k * 2 + d) * CIN + c] = Ws[i];
    }
    __syncthreads();
    int n = blockIdx.x * blockDim.x + threadIdx.x;
    if (n >= N) return;

    int idxs[27];
#pragma unroll
    for (int k = 0; k < 27; ++k) idxs[k] = nbr[n * 27 + k];
    bool live[27];
#pragma unroll
    for (int k = 0; k < 27; ++k) {
        bool v = (unsigned)idxs[k] < (unsigned)N;
        if (ACT) v = v && (act[idxs[k]] != 0);
        live[k] = v;
    }

    float a0 = 0.f, a1 = 0.f;
#pragma unroll
    for (int k = 0; k < 27; ++k) {
        if (live[k]) {
            const float4* fr = reinterpret_cast<const float4*>(feat + (size_t)idxs[k] * CIN);
            const float4* w0 = reinterpret_cast<const float4*>(sW + (k * 2 + 0) * CIN);
            const float4* w1 = reinterpret_cast<const float4*>(sW + (k * 2 + 1) * CIN);
#pragma unroll
            for (int j = 0; j < CIN / 4; ++j) {
                float4 v = fr[j], x = w0[j], y = w1[j];
                a0 += v.x * x.x + v.y * x.y + v.z * x.z + v.w * x.w;
                a1 += v.x * y.x + v.y * y.y + v.z * y.z + v.w * y.w;
            }
        }
    }
    ppn[(size_t)n * 6 + 0] = (float)coords[n * 4 + 0];
    ppn[(size_t)n * 6 + 1] = (float)coords[n * 4 + 1];
    ppn[(size_t)n * 6 + 2] = (float)coords[n * 4 + 2];
    ppn[(size_t)n * 6 + 3] = (float)coords[n * 4 + 3];
    ppn[(size_t)n * 6 + 4] = a0;
    ppn[(size_t)n * 6 + 5] = a1;
    float p = 1.f / (1.f + expf(a0 - a1));
    mask[n] = (p > 0.8f) ? 1.f : 0.f;
}

// Fine heads fused, batched pointer-chase: points[n, 0:3|3:5|5:10].
__global__ void heads_kernel(const float* __restrict__ z,
                             const int* __restrict__ nbr,
                             const float* __restrict__ Wp,
                             const float* __restrict__ Wsc,
                             const float* __restrict__ Wt,
                             const unsigned char* __restrict__ act,
                             float* __restrict__ points, int N) {
    __shared__ float sW[27 * 10 * 16];  // [k][d][c]
    for (int i = threadIdx.x; i < 27 * 16 * 3; i += blockDim.x) {
        int k = i / 48; int r = i - k * 48; int c = r / 3; int d = r - c * 3;
        sW[(k * 10 + d) * 16 + c] = Wp[i];
    }
    for (int i = threadIdx.x; i < 27 * 16 * 2; i += blockDim.x) {
        int k = i / 32; int r = i - k * 32; int c = r >> 1; int d = r & 1;
        sW[(k * 10 + 3 + d) * 16 + c] = Wsc[i];
    }
    for (int i = threadIdx.x; i < 27 * 16 * 5; i += blockDim.x) {
        int k = i / 80; int r = i - k * 80; int c = r / 5; int d = r - c * 5;
        sW[(k * 10 + 5 + d) * 16 + c] = Wt[i];
    }
    __syncthreads();
    int n = blockIdx.x * blockDim.x + threadIdx.x;
    if (n >= N) return;

    int idxs[27];
#pragma unroll
    for (int k = 0; k < 27; ++k) idxs[k] = nbr[n * 27 + k];
    bool live[27];
#pragma unroll
    for (int k = 0; k < 27; ++k)
        live[k] = ((unsigned)idxs[k] < (unsigned)N) && (act[idxs[k]] != 0);

    float acc[10];
#pragma unroll
    for (int d = 0; d < 10; ++d) acc[d] = 0.f;

#pragma unroll
    for (int k = 0; k < 27; ++k) {
        if (live[k]) {
            const float4* zr = reinterpret_cast<const float4*>(z + (size_t)idxs[k] * 16);
            float4 v0 = zr[0], v1 = zr[1], v2 = zr[2], v3 = zr[3];
#pragma unroll
            for (int d = 0; d < 10; ++d) {
                const float4* wr = reinterpret_cast<const float4*>(sW + (k * 10 + d) * 16);
                float4 w0 = wr[0], w1 = wr[1], w2 = wr[2], w3 = wr[3];
                acc[d] += v0.x * w0.x + v0.y * w0.y + v0.z * w0.z + v0.w * w0.w
                        + v1.x * w1.x + v1.y * w1.y + v1.z * w1.z + v1.w * w1.w
                        + v2.x * w2.x + v2.y * w2.y + v2.z * w2.z + v2.w * w2.w
                        + v3.x * w3.x + v3.y * w3.y + v3.z * w3.z + v3.w * w3.w;
            }
        }
    }
#pragma unroll
    for (int d = 0; d < 10; ++d) points[(size_t)n * 10 + d] = acc[d];
}

// ---------------------------------------------------------------------------
static constexpr int smem_sub(int CCH, int COUT, int TN) {
    return (CCH * COUT + TN * (CCH + 4) + 32) * (int)sizeof(float);
}

extern "C" void kernel_launch(void* const* d_in, const int* in_sizes, int n_in,
                              void* d_out, int out_size) {
    const float* feat1 = (const float*)d_in[0];
    const float* feat2 = (const float*)d_in[1];
    const float* feat3 = (const float*)d_in[2];
    const float* W1  = (const float*)d_in[3];
    const float* W1s = (const float*)d_in[4];
    const float* W2  = (const float*)d_in[5];
    const float* W2s = (const float*)d_in[6];
    const float* W3  = (const float*)d_in[7];
    const float* W3p = (const float*)d_in[8];
    const float* W3s = (const float*)d_in[9];
    const float* W3t = (const float*)d_in[10];
    const int* nbr1 = (const int*)d_in[11];
    const int* nbr2 = (const int*)d_in[12];
    const int* nbr3 = (const int*)d_in[13];
    const int* parent2 = (const int*)d_in[14];
    const int* parent3 = (const int*)d_in[15];
    const int* coords1 = (const int*)d_in[16];
    const int* coords2 = (const int*)d_in[17];

    const int N1 = in_sizes[0] / 80;
    const int N2 = in_sizes[1] / 48;
    const int N3 = in_sizes[2] / 16;

    float* out = (float*)d_out;
    float* points = out;
    float* ppn1  = points + (size_t)N3 * 10;
    float* ppn2  = ppn1 + (size_t)N1 * 6;
    float* mask1 = ppn2 + (size_t)N2 * 6;
    float* mask2 = mask1 + N1;

    float *y1, *y1p, *y2, *z, *pm2, *pm3;
    unsigned char *act2, *act3;
    cudaGetSymbolAddress((void**)&y1, g_y1);
    cudaGetSymbolAddress((void**)&y1p, g_y1p);
    cudaGetSymbolAddress((void**)&y2, g_y2);
    cudaGetSymbolAddress((void**)&z, g_z);
    cudaGetSymbolAddress((void**)&pm2, g_pm2);
    cudaGetSymbolAddress((void**)&pm3, g_pm3);
    cudaGetSymbolAddress((void**)&act2, g_act2);
    cudaGetSymbolAddress((void**)&act3, g_act3);

    // --- Level 1 (coarse, 80ch): K-split x4 conv + partial reduce ---
    {
        dim3 grid((N1 + 127) / 128, KSPLIT);
        subconv2k<80, 80, 128, 4, 20, 4, 40, 4>
            <<<grid, 128, smem_sub(40, 80, 128)>>>(
                feat1, nbr1, W1, y1p, (size_t)N1 * 80, N1);
        int total4 = N1 * 80 / 4;
        add_partials<<<(total4 + 255) / 256, 256>>>(
            y1p, (size_t)N1 * 80, y1, total4);
    }
    score_ppn_mask<80, false><<<(N1 + 255) / 256, 256>>>(
        y1, nbr1, W1s, coords1, nullptr, ppn1, mask1, N1);

    // --- Level 2 (mid, 48ch): pm2 precompute + proven conv (minBlocks=5) ---
    premask<<<(N2 + 255) / 256, 256>>>(parent2, mask1, pm2, N2);
    subconv2m<48, 48, 128, 4, 12, 4, 5>
        <<<(N2 + 127) / 128, 128, smem_sub(48, 48, 128)>>>(
            feat2, nbr2, W2, pm2, y2, act2, N2);
    score_ppn_mask<48, true><<<(N2 + 255) / 256, 256>>>(
        y2, nbr2, W2s, coords2, act2, ppn2, mask2, N2);

    // --- Level 3 (fine, 16ch): pm3 precompute + masked conv + act flags ---
    premask<<<(N3 + 255) / 256, 256>>>(parent3, mask2, pm3, N3);
    subconv2m<16, 16, 256, 8, 4, 4, 1>
        <<<(N3 + 255) / 256, 128, smem_sub(16, 16, 256)>>>(
            feat3, nbr3, W3, pm3, z, act3, N3);
    heads_kernel<<<(N3 + 255) / 256, 256>>>(
        z, nbr3, W3p, W3s, W3t, act3, points, N3);
}

// round 17
// speedup vs baseline: 1.8811x; 1.4246x over previous
#include <cuda_runtime.h>

// ---------------------------------------------------------------------------
// PPN on 3-level sparse voxel grid — FFMA2 convs + exact sparsity skips.
// R17: deterministic ROW COMPACTION for masked convs (compute only rows with
// an active neighbor; exact — inactive rows are never read downstream),
// flag-gated so an all-zero mask level costs ~nothing. L1 K-split kept.
// output: points [N3,10] | ppn1 [N1,6] | ppn2 [N2,6] | mask1 [N1] | mask2 [N2]
// ---------------------------------------------------------------------------

#define N1_MAX 65536
#define N2_MAX 262144
#define N3_MAX 262144
#define KSPLIT 4

__device__ float g_y1[(size_t)N1_MAX * 80];
__device__ float g_y1p[(size_t)KSPLIT * N1_MAX * 80];
__device__ float g_y2[(size_t)N2_MAX * 48];
__device__ float g_z[(size_t)N3_MAX * 16];
__device__ float g_pm2[N2_MAX];
__device__ float g_pm3[N3_MAX];
__device__ unsigned char g_act2[N2_MAX];
__device__ unsigned char g_act3[N3_MAX];
__device__ int g_list2[N2_MAX];
__device__ int g_list3[N3_MAX];
__device__ int g_bcnt2[1024], g_boff2[1024], g_cnt2[1];
__device__ int g_bcnt3[1024], g_boff3[1024], g_cnt3[1];
__device__ int g_flag2[1], g_flag3[1];

typedef unsigned long long ull;

__device__ __forceinline__ ull pk2(float x, float y) {
    ull r; asm("mov.b64 %0, {%1, %2};" : "=l"(r) : "f"(x), "f"(y)); return r;
}
__device__ __forceinline__ void fma2(ull& d, ull a, ull b) {
    asm("fma.rn.f32x2 %0, %1, %2, %0;" : "+l"(d) : "l"(a), "l"(b));
}
__device__ __forceinline__ float2 up2(ull v) {
    float a, b; asm("mov.b64 {%0, %1}, %2;" : "=f"(a), "=f"(b) : "l"(v));
    return make_float2(a, b);
}

__global__ void init_flags(int* f2, int* f3) {
    if (threadIdx.x == 0) { *f2 = 0; *f3 = 0; }
}

// pm[i] = mask[parent[i]]; sets *flag if any pm nonzero (warp-aggregated).
__global__ void premask_flag(const int* __restrict__ parent,
                             const float* __restrict__ mask,
                             float* __restrict__ pm, int* flag, int N) {
    int i = blockIdx.x * blockDim.x + threadIdx.x;
    float m = 0.f;
    if (i < N) { m = mask[parent[i]]; pm[i] = m; }
    unsigned b = __ballot_sync(0xffffffffu, m != 0.f);
    if ((threadIdx.x & 31) == 0 && b) atomicOr(flag, 1);
}

// act[n] = OR_k (pm[nbr[n,k]] != 0); per-block active count. Flag-gated.
__global__ void rowact_count(const int* __restrict__ nbr,
                             const float* __restrict__ pm,
                             const int* __restrict__ flag,
                             unsigned char* __restrict__ act,
                             int* __restrict__ bcnt, int N) {
    int n = blockIdx.x * 256 + threadIdx.x;
    int a = 0;
    if (*flag && n < N) {
        for (int k = 0; k < 27; ++k) {
            int idx = nbr[n * 27 + k];
            if ((unsigned)idx < (unsigned)N && pm[idx] != 0.f) { a = 1; break; }
        }
    }
    if (n < N) act[n] = (unsigned char)a;
    int c = __syncthreads_count(a);
    if (threadIdx.x == 0) bcnt[blockIdx.x] = c;
}

// Single-block scan of per-block counts -> exclusive offsets + total.
__global__ void scan_counts(const int* __restrict__ bcnt, int nb,
                            int* __restrict__ boff, int* __restrict__ total) {
    __shared__ int s[1024];
    int t = threadIdx.x;
    int v = (t < nb) ? bcnt[t] : 0;
    s[t] = v;
    __syncthreads();
    for (int off = 1; off < 1024; off <<= 1) {
        int x = (t >= off) ? s[t - off] : 0;
        __syncthreads();
        s[t] += x;
        __syncthreads();
    }
    if (t < nb) boff[t] = s[t] - v;
    if (t == nb - 1) *total = s[t];
}

// Scatter active row ids into list at deterministic positions.
__global__ void scatter_rows(const unsigned char* __restrict__ act,
                             const int* __restrict__ boff,
                             int* __restrict__ list, int N) {
    int n = blockIdx.x * 256 + threadIdx.x;
    int a = (n < N) ? (act[n] != 0) : 0;
    unsigned m = __ballot_sync(0xffffffffu, a);
    __shared__ int wcnt[8], woff[8];
    int w = threadIdx.x >> 5, l = threadIdx.x & 31;
    if (l == 0) wcnt[w] = __popc(m);
    __syncthreads();
    if (threadIdx.x == 0) {
        int s = 0;
        for (int j = 0; j < 8; ++j) { woff[j] = s; s += wcnt[j]; }
    }
    __syncthreads();
    if (a) list[boff[blockIdx.x] + woff[w] + __popc(m & ((1u << l) - 1u))] = n;
}

// y[i] = sum of KSPLIT partials (float4-vectorized)
__global__ void add_partials(const float* __restrict__ p, size_t pstride,
                             float* __restrict__ y, int total4) {
    int i = blockIdx.x * blockDim.x + threadIdx.x;
    if (i >= total4) return;
    float4 s = reinterpret_cast<const float4*>(p)[i];
#pragma unroll
    for (int j = 1; j < KSPLIT; ++j) {
        float4 v = reinterpret_cast<const float4*>(p + j * pstride)[i];
        s.x += v.x; s.y += v.y; s.z += v.z; s.w += v.w;
    }
    reinterpret_cast<float4*>(y)[i] = s;
}

// ---------------------------------------------------------------------------
// Unmasked conv, K-SPLIT (level 1): blockIdx.y = ks handles k in
// [7ks, min(27, 7ks+7)), accumulating into its own partial buffer.
// ---------------------------------------------------------------------------
template <int CIN, int COUT, int TN, int RN, int RD, int NTX, int CCH, int MINB>
__global__ __launch_bounds__(NTX*(TN/RN), MINB)
void subconv2k(const float* __restrict__ feat, const int* __restrict__ nbr,
               const float* __restrict__ W, float* __restrict__ outp,
               size_t pstride, int N) {
    constexpr int CP = CCH + 4;
    constexpr int NTY = TN / RN;
    constexpr int NTH = NTX * NTY;
    static_assert(NTH == 128, "128 threads");
    static_assert(CIN % CCH == 0 && CCH % 4 == 0 && RD % 4 == 0, "");
    constexpr int NH = CIN / CCH;
    constexpr int VEC = CCH / 4;
    constexpr int W4 = CCH * COUT / 4;
    constexpr int NP = RD / 2;
    constexpr int NU = RD / 4;

    extern __shared__ float sh[];
    float* sW = sh;
    float* sF = sh + CCH * COUT;
    __shared__ int sIdx[TN];

    const int tid = threadIdx.x;
    const int tx = tid % NTX, ty = tid / NTX;
    const int n0 = blockIdx.x * TN;
    const int nb = ty * RN, db = tx * RD;
    const int ks = blockIdx.y;
    const int kBeg = ks * 7, kEnd = (kBeg + 7 < 27) ? kBeg + 7 : 27;
    float* out = outp + (size_t)ks * pstride;

    ull acc[RN][NP];
#pragma unroll
    for (int i = 0; i < RN; ++i)
#pragma unroll
        for (int p = 0; p < NP; ++p) acc[i][p] = 0ULL;

    for (int k = kBeg; k < kEnd; ++k) {
        for (int i = tid; i < TN; i += NTH) {
            int n = n0 + i;
            sIdx[i] = (n < N) ? nbr[n * 27 + k] : N;
        }
        const float* Wk = W + (size_t)k * CIN * COUT;
#pragma unroll
        for (int h = 0; h < NH; ++h) {
            __syncthreads();
            {
                const float4* Wk4 = reinterpret_cast<const float4*>(
                    Wk + h * CCH * COUT);
                float4* sW4 = reinterpret_cast<float4*>(sW);
                for (int i = tid; i < W4; i += NTH) sW4[i] = Wk4[i];
            }
            const int bc = h * CCH;
            for (int i = tid; i < TN * VEC; i += NTH) {
                int n = i / VEC, c4 = (i - n * VEC) * 4;
                int idx = sIdx[n];
                float4 v = make_float4(0.f, 0.f, 0.f, 0.f);
                if ((unsigned)idx < (unsigned)N)
                    v = *reinterpret_cast<const float4*>(
                        feat + (size_t)idx * CIN + bc + c4);
                *reinterpret_cast<float4*>(sF + n * CP + c4) = v;
            }
            __syncthreads();

#pragma unroll
            for (int c4 = 0; c4 < CCH; c4 += 4) {
                float4 A[RN];
#pragma unroll
                for (int i = 0; i < RN; ++i)
                    A[i] = *reinterpret_cast<const float4*>(
                        sF + (nb + i) * CP + c4);
#pragma unroll
                for (int cc = 0; cc < 4; ++cc) {
                    ull as[RN];
#pragma unroll
                    for (int i = 0; i < RN; ++i) {
                        float v = (cc == 0) ? A[i].x : (cc == 1) ? A[i].y
                                 : (cc == 2) ? A[i].z : A[i].w;
                        as[i] = pk2(v, v);
                    }
                    const float* wrow = sW + (c4 + cc) * COUT + db;
#pragma unroll
                    for (int u = 0; u < NU; ++u) {
                        float4 B = *reinterpret_cast<const float4*>(wrow + 4 * u);
                        ull b0 = pk2(B.x, B.y), b1 = pk2(B.z, B.w);
#pragma unroll
                        for (int i = 0; i < RN; ++i) {
                            fma2(acc[i][2 * u], as[i], b0);
                            fma2(acc[i][2 * u + 1], as[i], b1);
                        }
                    }
                }
            }
        }
    }

#pragma unroll
    for (int i = 0; i < RN; ++i) {
        int n = n0 + nb + i;
        if (n < N) {
#pragma unroll
            for (int u = 0; u < NU; ++u) {
                float2 p0 = up2(acc[i][2 * u]), p1 = up2(acc[i][2 * u + 1]);
                float4 o = make_float4(p0.x, p0.y, p1.x, p1.y);
                *reinterpret_cast<float4*>(out + (size_t)n * COUT + db + 4 * u) = o;
            }
        }
    }
}

// ---------------------------------------------------------------------------
// COMPACTED masked conv: block b handles rows list[b*TN .. b*TN+TN) (cnt
// bounds); blocks past cnt exit. Per-stage all-zero-mask tiles skipped.
// out[rn,d] = sum_k sum_c pm[j]*feat[j,c]*W[k,c,d], j=nbr[rn,k].
// ---------------------------------------------------------------------------
template <int CIN, int COUT, int TN, int RN, int RD, int NTX, int MINB>
__global__ __launch_bounds__(NTX*(TN/RN), MINB)
void subconv2c(const float* __restrict__ feat, const int* __restrict__ nbr,
               const float* __restrict__ W, const float* __restrict__ pm,
               const int* __restrict__ list, const int* __restrict__ cntPtr,
               float* __restrict__ out, int N) {
    constexpr int CP = CIN + 4;
    constexpr int NTY = TN / RN;
    constexpr int NTH = NTX * NTY;
    static_assert(NTH == 128 || NTH == 256, "thread count");
    static_assert(CIN % 4 == 0 && RD % 4 == 0 && TN % NTH == 0, "");
    constexpr int VEC = CIN / 4;
    constexpr int W4 = CIN * COUT / 4;
    constexpr int NP = RD / 2;
    constexpr int NU = RD / 4;
    constexpr int RPT = TN / NTH;

    const int cnt = *cntPtr;
    const int n0 = blockIdx.x * TN;
    if (n0 >= cnt) return;

    extern __shared__ float sh[];
    float* sW = sh;                        // [CIN][COUT]
    float* sF = sh + CIN * COUT;           // [TN][CP]
    __shared__ int sRow[TN];
    __shared__ int sIdx[TN];
    __shared__ float sM[TN];

    const int tid = threadIdx.x;
    const int tx = tid % NTX, ty = tid / NTX;
    const int nb = ty * RN, db = tx * RD;

    for (int i = tid; i < TN; i += NTH) {
        int p = n0 + i;
        sRow[i] = (p < cnt) ? list[p] : -1;
    }
    __syncthreads();

    ull acc[RN][NP];
#pragma unroll
    for (int i = 0; i < RN; ++i)
#pragma unroll
        for (int p = 0; p < NP; ++p) acc[i][p] = 0ULL;

    for (int k = 0; k < 27; ++k) {
        int myAny = 0;
#pragma unroll
        for (int j = 0; j < RPT; ++j) {
            int i = tid + j * NTH;
            int rn = sRow[i];
            int idx = (rn >= 0) ? nbr[(size_t)rn * 27 + k] : N;
            float m = ((unsigned)idx < (unsigned)N) ? pm[idx] : 0.f;
            sIdx[i] = idx;
            sM[i] = m;
            myAny |= (m != 0.f);
        }
        if (!__syncthreads_or(myAny)) continue;   // exact: zero contribution

        {
            const float4* Wk4 = reinterpret_cast<const float4*>(
                W + (size_t)k * CIN * COUT);
            float4* sW4 = reinterpret_cast<float4*>(sW);
            for (int i = tid; i < W4; i += NTH) sW4[i] = Wk4[i];
        }
        for (int i = tid; i < TN * VEC; i += NTH) {
            int n = i / VEC, c4 = (i - n * VEC) * 4;
            int idx = sIdx[n];
            float4 v = make_float4(0.f, 0.f, 0.f, 0.f);
            if ((unsigned)idx < (unsigned)N) {
                float m = sM[n];
                if (m != 0.f) {
                    v = *reinterpret_cast<const float4*>(
                        feat + (size_t)idx * CIN + c4);
                    v.x *= m; v.y *= m; v.z *= m; v.w *= m;
                }
            }
            *reinterpret_cast<float4*>(sF + n * CP + c4) = v;
        }
        __syncthreads();

#pragma unroll
        for (int c4 = 0; c4 < CIN; c4 += 4) {
            float4 A[RN];
#pragma unroll
            for (int i = 0; i < RN; ++i)
                A[i] = *reinterpret_cast<const float4*>(sF + (nb + i) * CP + c4);
#pragma unroll
            for (int cc = 0; cc < 4; ++cc) {
                ull as[RN];
#pragma unroll
                for (int i = 0; i < RN; ++i) {
                    float v = (cc == 0) ? A[i].x : (cc == 1) ? A[i].y
                             : (cc == 2) ? A[i].z : A[i].w;
                    as[i] = pk2(v, v);
                }
                const float* wrow = sW + (c4 + cc) * COUT + db;
#pragma unroll
                for (int u = 0; u < NU; ++u) {
                    float4 B = *reinterpret_cast<const float4*>(wrow + 4 * u);
                    ull b0 = pk2(B.x, B.y), b1 = pk2(B.z, B.w);
#pragma unroll
                    for (int i = 0; i < RN; ++i) {
                        fma2(acc[i][2 * u], as[i], b0);
                        fma2(acc[i][2 * u + 1], as[i], b1);
                    }
                }
            }
        }
        __syncthreads();   // all reads done before next stage's sF/sW rewrite
    }

#pragma unroll
    for (int i = 0; i < RN; ++i) {
        int p = n0 + nb + i;
        if (p < cnt) {
            int rn = sRow[nb + i];
#pragma unroll
            for (int u = 0; u < NU; ++u) {
                float2 p0 = up2(acc[i][2 * u]), p1 = up2(acc[i][2 * u + 1]);
                float4 o = make_float4(p0.x, p0.y, p1.x, p1.y);
                *reinterpret_cast<float4*>(out + (size_t)rn * COUT + db + 4 * u) = o;
            }
        }
    }
}

// ---------------------------------------------------------------------------
// Score head (Cout=2) + ppn concat + threshold mask — batched pointer-chase.
// softmax([s0,s1])[1] > 0.8  <=>  1/(1+exp(s0-s1)) > 0.8
// ---------------------------------------------------------------------------
template <int CIN, bool ACT>
__global__ void score_ppn_mask(const float* __restrict__ feat,
                               const int* __restrict__ nbr,
                               const float* __restrict__ Ws,
                               const int* __restrict__ coords,
                               const unsigned char* __restrict__ act,
                               float* __restrict__ ppn,
                               float* __restrict__ mask, int N) {
    extern __shared__ float sWdyn[];
    float* sW = sWdyn;                      // [k][d][c]
    for (int i = threadIdx.x; i < 27 * CIN * 2; i += blockDim.x) {
        int k = i / (CIN * 2);
        int r = i - k * (CIN * 2);
        int c = r >> 1, d = r & 1;
        sW[(k * 2 + d) * CIN + c] = Ws[i];
    }
    __syncthreads();
    int n = blockIdx.x * blockDim.x + threadIdx.x;
    if (n >= N) return;

    int idxs[27];
#pragma unroll
    for (int k = 0; k < 27; ++k) idxs[k] = nbr[n * 27 + k];
    bool live[27];
#pragma unroll
    for (int k = 0; k < 27; ++k) {
        bool v = (unsigned)idxs[k] < (unsigned)N;
        if (ACT) v = v && (act[idxs[k]] != 0);
        live[k] = v;
    }

    float a0 = 0.f, a1 = 0.f;
#pragma unroll
    for (int k = 0; k < 27; ++k) {
        if (live[k]) {
            const float4* fr = reinterpret_cast<const float4*>(feat + (size_t)idxs[k] * CIN);
            const float4* w0 = reinterpret_cast<const float4*>(sW + (k * 2 + 0) * CIN);
            const float4* w1 = reinterpret_cast<const float4*>(sW + (k * 2 + 1) * CIN);
#pragma unroll
            for (int j = 0; j < CIN / 4; ++j) {
                float4 v = fr[j], x = w0[j], y = w1[j];
                a0 += v.x * x.x + v.y * x.y + v.z * x.z + v.w * x.w;
                a1 += v.x * y.x + v.y * y.y + v.z * y.z + v.w * y.w;
            }
        }
    }
    ppn[(size_t)n * 6 + 0] = (float)coords[n * 4 + 0];
    ppn[(size_t)n * 6 + 1] = (float)coords[n * 4 + 1];
    ppn[(size_t)n * 6 + 2] = (float)coords[n * 4 + 2];
    ppn[(size_t)n * 6 + 3] = (float)coords[n * 4 + 3];
    ppn[(size_t)n * 6 + 4] = a0;
    ppn[(size_t)n * 6 + 5] = a1;
    float p = 1.f / (1.f + expf(a0 - a1));
    mask[n] = (p > 0.8f) ? 1.f : 0.f;
}

// Fine heads fused, batched pointer-chase: points[n, 0:3|3:5|5:10].
__global__ void heads_kernel(const float* __restrict__ z,
                             const int* __restrict__ nbr,
                             const float* __restrict__ Wp,
                             const float* __restrict__ Wsc,
                             const float* __restrict__ Wt,
                             const unsigned char* __restrict__ act,
                             float* __restrict__ points, int N) {
    __shared__ float sW[27 * 10 * 16];  // [k][d][c]
    for (int i = threadIdx.x; i < 27 * 16 * 3; i += blockDim.x) {
        int k = i / 48; int r = i - k * 48; int c = r / 3; int d = r - c * 3;
        sW[(k * 10 + d) * 16 + c] = Wp[i];
    }
    for (int i = threadIdx.x; i < 27 * 16 * 2; i += blockDim.x) {
        int k = i / 32; int r = i - k * 32; int c = r >> 1; int d = r & 1;
        sW[(k * 10 + 3 + d) * 16 + c] = Wsc[i];
    }
    for (int i = threadIdx.x; i < 27 * 16 * 5; i += blockDim.x) {
        int k = i / 80; int r = i - k * 80; int c = r / 5; int d = r - c * 5;
        sW[(k * 10 + 5 + d) * 16 + c] = Wt[i];
    }
    __syncthreads();
    int n = blockIdx.x * blockDim.x + threadIdx.x;
    if (n >= N) return;

    int idxs[27];
#pragma unroll
    for (int k = 0; k < 27; ++k) idxs[k] = nbr[n * 27 + k];
    bool live[27];
#pragma unroll
    for (int k = 0; k < 27; ++k)
        live[k] = ((unsigned)idxs[k] < (unsigned)N) && (act[idxs[k]] != 0);

    float acc[10];
#pragma unroll
    for (int d = 0; d < 10; ++d) acc[d] = 0.f;

#pragma unroll
    for (int k = 0; k < 27; ++k) {
        if (live[k]) {
            const float4* zr = reinterpret_cast<const float4*>(z + (size_t)idxs[k] * 16);
            float4 v0 = zr[0], v1 = zr[1], v2 = zr[2], v3 = zr[3];
#pragma unroll
            for (int d = 0; d < 10; ++d) {
                const float4* wr = reinterpret_cast<const float4*>(sW + (k * 10 + d) * 16);
                float4 w0 = wr[0], w1 = wr[1], w2 = wr[2], w3 = wr[3];
                acc[d] += v0.x * w0.x + v0.y * w0.y + v0.z * w0.z + v0.w * w0.w
                        + v1.x * w1.x + v1.y * w1.y + v1.z * w1.z + v1.w * w1.w
                        + v2.x * w2.x + v2.y * w2.y + v2.z * w2.z + v2.w * w2.w
                        + v3.x * w3.x + v3.y * w3.y + v3.z * w3.z + v3.w * w3.w;
            }
        }
    }
#pragma unroll
    for (int d = 0; d < 10; ++d) points[(size_t)n * 10 + d] = acc[d];
}

// ---------------------------------------------------------------------------
static constexpr int smem_sub(int CCH, int COUT, int TN) {
    return (CCH * COUT + TN * (CCH + 4) + 32) * (int)sizeof(float);
}

extern "C" void kernel_launch(void* const* d_in, const int* in_sizes, int n_in,
                              void* d_out, int out_size) {
    const float* feat1 = (const float*)d_in[0];
    const float* feat2 = (const float*)d_in[1];
    const float* feat3 = (const float*)d_in[2];
    const float* W1  = (const float*)d_in[3];
    const float* W1s = (const float*)d_in[4];
    const float* W2  = (const float*)d_in[5];
    const float* W2s = (const float*)d_in[6];
    const float* W3  = (const float*)d_in[7];
    const float* W3p = (const float*)d_in[8];
    const float* W3s = (const float*)d_in[9];
    const float* W3t = (const float*)d_in[10];
    const int* nbr1 = (const int*)d_in[11];
    const int* nbr2 = (const int*)d_in[12];
    const int* nbr3 = (const int*)d_in[13];
    const int* parent2 = (const int*)d_in[14];
    const int* parent3 = (const int*)d_in[15];
    const int* coords1 = (const int*)d_in[16];
    const int* coords2 = (const int*)d_in[17];

    const int N1 = in_sizes[0] / 80;
    const int N2 = in_sizes[1] / 48;
    const int N3 = in_sizes[2] / 16;

    float* out = (float*)d_out;
    float* points = out;
    float* ppn1  = points + (size_t)N3 * 10;
    float* ppn2  = ppn1 + (size_t)N1 * 6;
    float* mask1 = ppn2 + (size_t)N2 * 6;
    float* mask2 = mask1 + N1;

    float *y1, *y1p, *y2, *z, *pm2, *pm3;
    unsigned char *act2, *act3;
    int *list2, *list3, *bcnt2, *boff2, *cnt2, *bcnt3, *boff3, *cnt3, *f2, *f3;
    cudaGetSymbolAddress((void**)&y1, g_y1);
    cudaGetSymbolAddress((void**)&y1p, g_y1p);
    cudaGetSymbolAddress((void**)&y2, g_y2);
    cudaGetSymbolAddress((void**)&z, g_z);
    cudaGetSymbolAddress((void**)&pm2, g_pm2);
    cudaGetSymbolAddress((void**)&pm3, g_pm3);
    cudaGetSymbolAddress((void**)&act2, g_act2);
    cudaGetSymbolAddress((void**)&act3, g_act3);
    cudaGetSymbolAddress((void**)&list2, g_list2);
    cudaGetSymbolAddress((void**)&list3, g_list3);
    cudaGetSymbolAddress((void**)&bcnt2, g_bcnt2);
    cudaGetSymbolAddress((void**)&boff2, g_boff2);
    cudaGetSymbolAddress((void**)&cnt2, g_cnt2);
    cudaGetSymbolAddress((void**)&bcnt3, g_bcnt3);
    cudaGetSymbolAddress((void**)&boff3, g_boff3);
    cudaGetSymbolAddress((void**)&cnt3, g_cnt3);
    cudaGetSymbolAddress((void**)&f2, g_flag2);
    cudaGetSymbolAddress((void**)&f3, g_flag3);

    init_flags<<<1, 32>>>(f2, f3);

    // --- Level 1 (coarse, 80ch): K-split x4 conv + partial reduce ---
    {
        dim3 grid((N1 + 127) / 128, KSPLIT);
        subconv2k<80, 80, 128, 4, 20, 4, 40, 4>
            <<<grid, 128, smem_sub(40, 80, 128)>>>(
                feat1, nbr1, W1, y1p, (size_t)N1 * 80, N1);
        int total4 = N1 * 80 / 4;
        add_partials<<<(total4 + 255) / 256, 256>>>(
            y1p, (size_t)N1 * 80, y1, total4);
    }
    score_ppn_mask<80, false><<<(N1 + 63) / 64, 64,
        27 * 2 * 80 * sizeof(float)>>>(
        y1, nbr1, W1s, coords1, nullptr, ppn1, mask1, N1);

    // --- Level 2 (mid, 48ch): compaction + compacted conv ---
    {
        int nb = (N2 + 255) / 256;
        premask_flag<<<nb, 256>>>(parent2, mask1, pm2, f2, N2);
        rowact_count<<<nb, 256>>>(nbr2, pm2, f2, act2, bcnt2, N2);
        scan_counts<<<1, 1024>>>(bcnt2, nb, boff2, cnt2);
        scatter_rows<<<nb, 256>>>(act2, boff2, list2, N2);
        subconv2c<48, 48, 128, 4, 12, 4, 5>
            <<<(N2 + 127) / 128, 128, smem_sub(48, 48, 128)>>>(
                feat2, nbr2, W2, pm2, list2, cnt2, y2, N2);
    }
    score_ppn_mask<48, true><<<(N2 + 255) / 256, 256,
        27 * 2 * 48 * sizeof(float)>>>(
        y2, nbr2, W2s, coords2, act2, ppn2, mask2, N2);

    // --- Level 3 (fine, 16ch): compaction (flag-gated) + compacted conv ---
    {
        int nb = (N3 + 255) / 256;
        premask_flag<<<nb, 256>>>(parent3, mask2, pm3, f3, N3);
        rowact_count<<<nb, 256>>>(nbr3, pm3, f3, act3, bcnt3, N3);
        scan_counts<<<1, 1024>>>(bcnt3, nb, boff3, cnt3);
        scatter_rows<<<nb, 256>>>(act3, boff3, list3, N3);
        subconv2c<16, 16, 256, 8, 4, 4, 1>
            <<<(N3 + 255) / 256, 128, smem_sub(16, 16, 256)>>>(
                feat3, nbr3, W3, pm3, list3, cnt3, z, N3);
    }
    heads_kernel<<<(N3 + 255) / 256, 256>>>(
        z, nbr3, W3p, W3s, W3t, act3, points, N3);
}